// round 10
// baseline (speedup 1.0000x reference)
#include <cuda_runtime.h>
#include <math.h>

// Problem dims
#define BATCH 32
#define TT    1024
#define DD    512
#define HH    512
#define GG    2048
#define LLAY  2
#define MM    (BATCH*TT)

// Output layout in d_out (float32): seq [B,T,H], then h [B,L,H], then c [B,L,H]
#define SEQ_ELEMS  ((size_t)MM*HH)
#define HOFF       (SEQ_ELEMS)
#define COFF       (SEQ_ELEMS + (size_t)BATCH*LLAY*HH)

// Recurrence config: 128 blocks = 32 unit-groups x 4 batch-groups
#define NBLK 128
#define NTHR 256
#define NBG  4
#define NUG  32
#define BPB  8      // batches per block

// Scratch (device globals) — 128B-aligned for cp.async.bulk
__device__ __align__(128) float g_xg[(size_t)MM*GG];
__device__ __align__(128) float g_seq0[(size_t)MM*HH];
__device__ __align__(128) float g_hbuf[2][BATCH*HH];
__device__ unsigned g_flags[NBG][NUG];
__device__ unsigned g_bar_count;
__device__ unsigned g_bar_gen;

// ---------------- packed f32x2 helpers ----------------
__device__ __forceinline__ unsigned long long ffma2(unsigned long long a,
                                                    unsigned long long b,
                                                    unsigned long long c)
{
    unsigned long long d;
    asm("fma.rn.f32x2 %0, %1, %2, %3;" : "=l"(d) : "l"(a), "l"(b), "l"(c));
    return d;
}
__device__ __forceinline__ unsigned long long pack2(float x, float y)
{
    unsigned long long d;
    asm("mov.b64 %0, {%1, %2};" : "=l"(d) : "f"(x), "f"(y));
    return d;
}
__device__ __forceinline__ float2 unpack2(unsigned long long v)
{
    float2 r;
    asm("mov.b64 {%0, %1}, %2;" : "=f"(r.x), "=f"(r.y) : "l"(v));
    return r;
}

// ---------------- fast activations (MUFU-based) ----------------
__device__ __forceinline__ float fsigmoid(float x)
{
    return __fdividef(1.f, 1.f + __expf(-x));
}
__device__ __forceinline__ float ftanh(float x)
{
    return 1.f - __fdividef(2.f, __expf(2.f * x) + 1.f);
}

// ---------------- acquire/release ----------------
__device__ __forceinline__ unsigned ld_acquire_gpu(const unsigned* p)
{
    unsigned v;
    asm volatile("ld.acquire.gpu.global.b32 %0, [%1];" : "=r"(v) : "l"(p) : "memory");
    return v;
}
__device__ __forceinline__ void st_release_gpu(unsigned* p, unsigned v)
{
    asm volatile("st.release.gpu.global.b32 [%0], %1;" :: "l"(p), "r"(v) : "memory");
}

// ---------------- mbarrier + bulk copy ----------------
__device__ __forceinline__ void mbar_init(unsigned mbar, unsigned count)
{
    asm volatile("mbarrier.init.shared.b64 [%0], %1;" :: "r"(mbar), "r"(count) : "memory");
}
__device__ __forceinline__ void mbar_expect_tx(unsigned mbar, unsigned bytes)
{
    asm volatile("mbarrier.arrive.expect_tx.shared.b64 _, [%0], %1;"
                 :: "r"(mbar), "r"(bytes) : "memory");
}
__device__ __forceinline__ void mbar_wait_parity(unsigned mbar, unsigned ph)
{
    asm volatile(
        "{\n\t"
        ".reg .pred P1;\n\t"
        "WAIT_LOOP_%=:\n\t"
        "mbarrier.try_wait.parity.acquire.cta.shared::cta.b64 P1, [%0], %1, 0x989680;\n\t"
        "@P1 bra.uni WAIT_DONE_%=;\n\t"
        "bra.uni WAIT_LOOP_%=;\n\t"
        "WAIT_DONE_%=:\n\t"
        "}"
        :: "r"(mbar), "r"(ph) : "memory");
}
__device__ __forceinline__ void bulk_g2s(unsigned smem_dst, const void* gsrc,
                                         unsigned bytes, unsigned mbar)
{
    asm volatile(
        "cp.async.bulk.shared::cluster.global.mbarrier::complete_tx::bytes "
        "[%0], [%1], %2, [%3];"
        :: "r"(smem_dst), "l"(gsrc), "r"(bytes), "r"(mbar) : "memory");
}

// ---------------------------------------------------------------------------
// SGEMM: C = A @ W + bias1 + bias2. 128x128 tile, BK=8, FFMA2,
// register double-buffer + 2x smem buffers: one __syncthreads per tile.
// ---------------------------------------------------------------------------
__global__ void __launch_bounds__(256, 2)
sgemm_bias(const float* __restrict__ A, const float* __restrict__ W,
           const float* __restrict__ bias1, const float* __restrict__ bias2,
           float* __restrict__ C, int Kdim)
{
    __shared__ __align__(16) float As[2][8][128];
    __shared__ __align__(16) float Bs[2][8][128];

    const int tid = threadIdx.x;
    const int brow = blockIdx.y, bcol = blockIdx.x;

    const float* Ablk = A + (size_t)brow * 128 * Kdim;
    const float* Wblk = W + (size_t)bcol * 128;

    const int arow = tid >> 1;
    const int ak4  = (tid & 1) * 4;
    const int wrow = tid >> 5;
    const int wn4  = (tid & 31) * 4;
    const int ty = tid >> 4;
    const int tx = tid & 15;

    const int KT = Kdim >> 3;

    unsigned long long acc[8][4];
#pragma unroll
    for (int i = 0; i < 8; i++)
#pragma unroll
        for (int j = 0; j < 4; j++) acc[i][j] = 0ull;

    float4 av = *(const float4*)(Ablk + (size_t)arow * Kdim + ak4);
    float4 wv = *(const float4*)(Wblk + (size_t)wrow * GG + wn4);
    As[0][ak4 + 0][arow] = av.x;
    As[0][ak4 + 1][arow] = av.y;
    As[0][ak4 + 2][arow] = av.z;
    As[0][ak4 + 3][arow] = av.w;
    *(float4*)(&Bs[0][wrow][wn4]) = wv;
    if (KT > 1) {
        av = *(const float4*)(Ablk + (size_t)arow * Kdim + 8 + ak4);
        wv = *(const float4*)(Wblk + (size_t)(8 + wrow) * GG + wn4);
    }
    __syncthreads();

    for (int kt = 0; kt < KT; kt++) {
        const int cur = kt & 1;

#pragma unroll
        for (int kk = 0; kk < 8; kk++) {
            float a[8];
            *(float4*)&a[0] = *(const float4*)&As[cur][kk][ty * 8];
            *(float4*)&a[4] = *(const float4*)&As[cur][kk][ty * 8 + 4];
            ulonglong2 b01 = *(const ulonglong2*)&Bs[cur][kk][tx * 8];
            ulonglong2 b23 = *(const ulonglong2*)&Bs[cur][kk][tx * 8 + 4];
            unsigned long long bd[4] = { b01.x, b01.y, b23.x, b23.y };
#pragma unroll
            for (int i = 0; i < 8; i++) {
                unsigned long long ad = pack2(a[i], a[i]);
#pragma unroll
                for (int j = 0; j < 4; j++)
                    acc[i][j] = ffma2(ad, bd[j], acc[i][j]);
            }
        }

        if (kt + 1 < KT) {
            const int nxt = (kt + 1) & 1;
            As[nxt][ak4 + 0][arow] = av.x;
            As[nxt][ak4 + 1][arow] = av.y;
            As[nxt][ak4 + 2][arow] = av.z;
            As[nxt][ak4 + 3][arow] = av.w;
            *(float4*)(&Bs[nxt][wrow][wn4]) = wv;
            if (kt + 2 < KT) {
                const int k0 = (kt + 2) * 8;
                av = *(const float4*)(Ablk + (size_t)arow * Kdim + k0 + ak4);
                wv = *(const float4*)(Wblk + (size_t)(k0 + wrow) * GG + wn4);
            }
            __syncthreads();
        }
    }

    const int row0 = brow * 128 + ty * 8;
    const int col0 = bcol * 128 + tx * 8;
    float bs[8];
#pragma unroll
    for (int j = 0; j < 8; j++) bs[j] = bias1[col0 + j] + bias2[col0 + j];

#pragma unroll
    for (int i = 0; i < 8; i++) {
        float c[8];
#pragma unroll
        for (int j = 0; j < 4; j++) {
            float2 v = unpack2(acc[i][j]);
            c[2*j]   = v.x + bs[2*j];
            c[2*j+1] = v.y + bs[2*j+1];
        }
        *(float4*)(C + (size_t)(row0 + i) * GG + col0)     = *(float4*)&c[0];
        *(float4*)(C + (size_t)(row0 + i) * GG + col0 + 4) = *(float4*)&c[4];
    }
}

// ---------------------------------------------------------------------------
// Startup-only grid barrier
// ---------------------------------------------------------------------------
__device__ __forceinline__ void grid_barrier()
{
    __syncthreads();
    if (threadIdx.x == 0) {
        __threadfence();
        volatile unsigned* vgen = &g_bar_gen;
        unsigned gen = *vgen;
        unsigned arrived = atomicAdd(&g_bar_count, 1u);
        if (arrived == gridDim.x - 1) {
            g_bar_count = 0;
            __threadfence();
            atomicAdd(&g_bar_gen, 1u);
        } else {
            while (*vgen == gen) { }
            __threadfence();
        }
    }
    __syncthreads();
}

// ---------------------------------------------------------------------------
// Persistent LSTM recurrence, chunk-pipelined h exchange.
// Block (ug, bg): 16 units x 4 gates x 8 batches.
// h(t-1) arrives in 4 chunks of 128 k-values: warp c (c<4) polls its 8
// producer flags, then lanes 0-7 issue 8 x 512B bulk copies to mbar[c].
// Compute consumes chunks in order, overlapping transfer + absorbing the
// slowest producer's jitter. Weights in registers, fused update via shfl.
// ---------------------------------------------------------------------------
__global__ void __launch_bounds__(NTHR, 1)
lstm_recur(const float* __restrict__ Wh_l,
           const float* __restrict__ xg,
           float* __restrict__ seq_out,
           float* __restrict__ hc_out,
           int layer)
{
    __shared__ __align__(128) float hs[BPB * 512];   // 16 KB staged h
    __shared__ __align__(8) unsigned long long mbar_store[4];

    const int tid  = threadIdx.x;
    const int wid  = tid >> 5, lane = tid & 31;
    const int ug   = blockIdx.x & 31;
    const int bg   = blockIdx.x >> 5;

    unsigned mbar_c[4];
#pragma unroll
    for (int c = 0; c < 4; c++)
        mbar_c[c] = (unsigned)__cvta_generic_to_shared(&mbar_store[c]);
    const unsigned hs_s = (unsigned)__cvta_generic_to_shared(hs);

    // compute mapping: warp = 2 units x 4 gates x 4 k-phases
    const int u2   = lane & 1;
    const int gate = (lane >> 1) & 3;
    const int s    = lane >> 3;             // k-phase 0..3
    const int ul   = (wid << 1) | u2;
    const int gcol = gate * 512 + ug * 16 + ul;

    // update mapping (lanes 0..15)
    const int uu   = (wid << 1) | (lane & 1);
    const int ubat = lane >> 1;
    const int bglob = bg * 8 + ubat;
    const int uglob = ug * 16 + uu;

    // ---- weights into registers: k = k4*16 + s*4 + {0..3} ----
    unsigned long long w2[64];
    {
#pragma unroll 8
        for (int k4 = 0; k4 < 32; k4++) {
            int kbase = k4 * 16 + s * 4;
            const float* wp = Wh_l + (size_t)kbase * GG + gcol;
            w2[2 * k4]     = pack2(wp[0],      wp[(size_t)GG]);
            w2[2 * k4 + 1] = pack2(wp[2 * GG], wp[(size_t)3 * GG]);
        }
    }

    // ---- init ----
    if (tid == 0) g_flags[bg][ug] = 0;
    if (wid == 0 && lane < 4) mbar_init(mbar_c[lane], 1);
    if (ug == 0) {
        float* hz = &g_hbuf[0][bg * 8 * 512];
        for (int i = tid; i < (8 * 512) / 4; i += NTHR)
            __stcg((float4*)hz + i, make_float4(0.f, 0.f, 0.f, 0.f));
    }
    __syncthreads();

    float creg = 0.f;

    grid_barrier();

    for (int t = 0; t < TT; t++) {
        // prefetch xg for my cell (4 gates), lanes 0..15
        float xgv[4] = {0.f, 0.f, 0.f, 0.f};
        if (lane < 16) {
            const float* xp = xg + ((size_t)bglob * TT + t) * GG + uglob;
            xgv[0] = __ldcg(xp);
            xgv[1] = __ldcg(xp + 512);
            xgv[2] = __ldcg(xp + 1024);
            xgv[3] = __ldcg(xp + 1536);
        }

        // ---- warps 0..3: poll chunk flags, then 8 x 512B bulk copies ----
        if (wid < 4) {
            if (t > 0) {
                const unsigned tok = (unsigned)t;
                const unsigned* fp = &g_flags[bg][wid * 8 + (lane & 7)];
                while (true) {
                    unsigned v = ld_acquire_gpu(fp);
                    if (__all_sync(0xffffffffu, v >= tok)) break;
                }
            }
            if (lane == 0)
                mbar_expect_tx(mbar_c[wid], 8 * 512);
            __syncwarp();
            if (lane < 8) {
                // row = batch (lane), chunk k-range = [wid*128, wid*128+128)
                bulk_g2s(hs_s + (unsigned)(lane * 2048 + wid * 512),
                         &g_hbuf[t & 1][(bg * 8 + lane) * 512 + wid * 128],
                         512, mbar_c[wid]);
            }
        }

        // ---- chunked dot products: consume chunks in order ----
        unsigned long long acc[8];
#pragma unroll
        for (int b = 0; b < 8; b++) acc[b] = 0ull;

#pragma unroll
        for (int c = 0; c < 4; c++) {
            mbar_wait_parity(mbar_c[c], (unsigned)(t & 1));
#pragma unroll
            for (int k4 = c * 8; k4 < c * 8 + 8; k4++) {
#pragma unroll
                for (int b = 0; b < 8; b++) {
                    ulonglong2 h2 = *(const ulonglong2*)&hs[b * 512 + k4 * 16 + s * 4];
                    acc[b] = ffma2(h2.x, w2[2 * k4], acc[b]);
                    acc[b] = ffma2(h2.y, w2[2 * k4 + 1], acc[b]);
                }
            }
        }

        // reduce across 4 k-phases (lane bits 3,4)
        float dot[8];
#pragma unroll
        for (int b = 0; b < 8; b++) {
            float2 p = unpack2(acc[b]);
            float v = p.x + p.y;
            v += __shfl_xor_sync(0xffffffffu, v, 8);
            v += __shfl_xor_sync(0xffffffffu, v, 16);
            dot[b] = v;
        }

        // transpose: lane L<16 gathers the 4 gate dots of (unit L&1, batch L>>1)
        float gv[4];
#pragma unroll
        for (int g = 0; g < 4; g++) {
            float got = 0.f;
#pragma unroll
            for (int b = 0; b < 8; b++) {
                float tv = __shfl_sync(0xffffffffu, dot[b], 2 * g + (lane & 1));
                if ((lane >> 1) == b) got = tv;
            }
            gv[g] = got;
        }

        // ---- cell update on lanes 0..15 of every warp ----
        float hval = 0.f;
        if (lane < 16) {
            float f  = fsigmoid(gv[0] + xgv[0]);
            float g  = ftanh   (gv[1] + xgv[1]);
            float ii = fsigmoid(gv[2] + xgv[2]);
            float o  = fsigmoid(gv[3] + xgv[3]);
            creg = f * creg + ii * g;
            hval = o * ftanh(creg);
        }
        // paired h store: even lane stores float2 {unit even, unit odd}
        float hpart = __shfl_xor_sync(0xffffffffu, hval, 1);
        if (lane < 16 && !(lane & 1)) {
            float2 v2 = make_float2(hval, hpart);
            __stcg((float2*)&g_hbuf[(t + 1) & 1][bglob * 512 + ug * 16 + (wid << 1)], v2);
        }
        __syncthreads();

        // ---- publish (release orders the h stores), then lazy outputs ----
        if (tid == 0)
            st_release_gpu(&g_flags[bg][ug], (unsigned)(t + 1));

        if (lane < 16) {
            seq_out[((size_t)bglob * TT + t) * HH + uglob] = hval;
            if (t == TT - 1) {
                hc_out[HOFF + (size_t)(bglob * LLAY + layer) * HH + uglob] = hval;
                hc_out[COFF + (size_t)(bglob * LLAY + layer) * HH + uglob] = creg;
            }
        }
    }
}

// ---------------------------------------------------------------------------
extern "C" void kernel_launch(void* const* d_in, const int* in_sizes, int n_in,
                              void* d_out, int out_size)
{
    const float* x  = (const float*)d_in[0];
    const float* Wx = (const float*)d_in[1];
    const float* bx = (const float*)d_in[2];
    const float* Wh = (const float*)d_in[3];
    const float* bh = (const float*)d_in[4];
    float* out = (float*)d_out;

    float *xg = nullptr, *seq0 = nullptr;
    cudaGetSymbolAddress((void**)&xg, g_xg);
    cudaGetSymbolAddress((void**)&seq0, g_seq0);

    dim3 gdim(GG / 128, MM / 128);

    // Layer 0
    sgemm_bias<<<gdim, 256>>>(x, Wx, bx, bh, xg, DD);
    lstm_recur<<<NBLK, NTHR>>>(Wh, xg, seq0, out, 0);

    // Layer 1
    sgemm_bias<<<gdim, 256>>>(seq0, Wx + (size_t)DD * GG, bx + GG, bh + GG, xg, HH);
    lstm_recur<<<NBLK, NTHR>>>(Wh + (size_t)HH * GG, xg, out, out, 1);
}

// round 13
// speedup vs baseline: 1.0417x; 1.0417x over previous
#include <cuda_runtime.h>
#include <math.h>

// Problem dims
#define BATCH 32
#define TT    1024
#define DD    512
#define HH    512
#define GG    2048
#define LLAY  2
#define MM    (BATCH*TT)

// Output layout in d_out (float32): seq [B,T,H], then h [B,L,H], then c [B,L,H]
#define SEQ_ELEMS  ((size_t)MM*HH)
#define HOFF       (SEQ_ELEMS)
#define COFF       (SEQ_ELEMS + (size_t)BATCH*LLAY*HH)

// Recurrence config: 128 blocks = 32 unit-groups x 4 batch-groups
#define NBLK 128
#define NTHR 256
#define NBG  4
#define NUG  32
#define BPB  8      // batches per block

// Scratch (device globals) — 128B-aligned for cp.async.bulk
__device__ __align__(128) float g_xg[(size_t)MM*GG];
__device__ __align__(128) float g_seq0[(size_t)MM*HH];
__device__ __align__(128) float g_hbuf[2][BATCH*HH];
__device__ unsigned g_flags[NBG][NUG];
__device__ unsigned g_bar_count;
__device__ unsigned g_bar_gen;

// ---------------- packed f32x2 helpers ----------------
__device__ __forceinline__ unsigned long long ffma2(unsigned long long a,
                                                    unsigned long long b,
                                                    unsigned long long c)
{
    unsigned long long d;
    asm("fma.rn.f32x2 %0, %1, %2, %3;" : "=l"(d) : "l"(a), "l"(b), "l"(c));
    return d;
}
__device__ __forceinline__ unsigned long long pack2(float x, float y)
{
    unsigned long long d;
    asm("mov.b64 %0, {%1, %2};" : "=l"(d) : "f"(x), "f"(y));
    return d;
}
__device__ __forceinline__ float2 unpack2(unsigned long long v)
{
    float2 r;
    asm("mov.b64 {%0, %1}, %2;" : "=f"(r.x), "=f"(r.y) : "l"(v));
    return r;
}

// ---------------- fast activations (MUFU-based) ----------------
__device__ __forceinline__ float fsigmoid(float x)
{
    return __fdividef(1.f, 1.f + __expf(-x));
}
__device__ __forceinline__ float ftanh(float x)
{
    return 1.f - __fdividef(2.f, __expf(2.f * x) + 1.f);
}

// ---------------- acquire/release ----------------
__device__ __forceinline__ unsigned ld_acquire_gpu(const unsigned* p)
{
    unsigned v;
    asm volatile("ld.acquire.gpu.global.b32 %0, [%1];" : "=r"(v) : "l"(p) : "memory");
    return v;
}
__device__ __forceinline__ void st_release_gpu(unsigned* p, unsigned v)
{
    asm volatile("st.release.gpu.global.b32 [%0], %1;" :: "l"(p), "r"(v) : "memory");
}

// ---------------- mbarrier + bulk copy ----------------
__device__ __forceinline__ void mbar_init(unsigned mbar, unsigned count)
{
    asm volatile("mbarrier.init.shared.b64 [%0], %1;" :: "r"(mbar), "r"(count) : "memory");
}
__device__ __forceinline__ void mbar_expect_tx(unsigned mbar, unsigned bytes)
{
    asm volatile("mbarrier.arrive.expect_tx.shared.b64 _, [%0], %1;"
                 :: "r"(mbar), "r"(bytes) : "memory");
}
__device__ __forceinline__ void mbar_wait_parity(unsigned mbar, unsigned ph)
{
    asm volatile(
        "{\n\t"
        ".reg .pred P1;\n\t"
        "WAIT_LOOP_%=:\n\t"
        "mbarrier.try_wait.parity.acquire.cta.shared::cta.b64 P1, [%0], %1, 0x989680;\n\t"
        "@P1 bra.uni WAIT_DONE_%=;\n\t"
        "bra.uni WAIT_LOOP_%=;\n\t"
        "WAIT_DONE_%=:\n\t"
        "}"
        :: "r"(mbar), "r"(ph) : "memory");
}
__device__ __forceinline__ void bulk_g2s(unsigned smem_dst, const void* gsrc,
                                         unsigned bytes, unsigned mbar)
{
    asm volatile(
        "cp.async.bulk.shared::cluster.global.mbarrier::complete_tx::bytes "
        "[%0], [%1], %2, [%3];"
        :: "r"(smem_dst), "l"(gsrc), "r"(bytes), "r"(mbar) : "memory");
}

// ---------------------------------------------------------------------------
// SGEMM: C = A @ W + bias1 + bias2. 128x128 tile, BK=8, FFMA2,
// register double-buffer + 2x smem buffers: one __syncthreads per tile.
// ---------------------------------------------------------------------------
__global__ void __launch_bounds__(256, 2)
sgemm_bias(const float* __restrict__ A, const float* __restrict__ W,
           const float* __restrict__ bias1, const float* __restrict__ bias2,
           float* __restrict__ C, int Kdim)
{
    __shared__ __align__(16) float As[2][8][128];
    __shared__ __align__(16) float Bs[2][8][128];

    const int tid = threadIdx.x;
    const int brow = blockIdx.y, bcol = blockIdx.x;

    const float* Ablk = A + (size_t)brow * 128 * Kdim;
    const float* Wblk = W + (size_t)bcol * 128;

    const int arow = tid >> 1;
    const int ak4  = (tid & 1) * 4;
    const int wrow = tid >> 5;
    const int wn4  = (tid & 31) * 4;
    const int ty = tid >> 4;
    const int tx = tid & 15;

    const int KT = Kdim >> 3;

    unsigned long long acc[8][4];
#pragma unroll
    for (int i = 0; i < 8; i++)
#pragma unroll
        for (int j = 0; j < 4; j++) acc[i][j] = 0ull;

    float4 av = *(const float4*)(Ablk + (size_t)arow * Kdim + ak4);
    float4 wv = *(const float4*)(Wblk + (size_t)wrow * GG + wn4);
    As[0][ak4 + 0][arow] = av.x;
    As[0][ak4 + 1][arow] = av.y;
    As[0][ak4 + 2][arow] = av.z;
    As[0][ak4 + 3][arow] = av.w;
    *(float4*)(&Bs[0][wrow][wn4]) = wv;
    if (KT > 1) {
        av = *(const float4*)(Ablk + (size_t)arow * Kdim + 8 + ak4);
        wv = *(const float4*)(Wblk + (size_t)(8 + wrow) * GG + wn4);
    }
    __syncthreads();

    for (int kt = 0; kt < KT; kt++) {
        const int cur = kt & 1;

#pragma unroll
        for (int kk = 0; kk < 8; kk++) {
            float a[8];
            *(float4*)&a[0] = *(const float4*)&As[cur][kk][ty * 8];
            *(float4*)&a[4] = *(const float4*)&As[cur][kk][ty * 8 + 4];
            ulonglong2 b01 = *(const ulonglong2*)&Bs[cur][kk][tx * 8];
            ulonglong2 b23 = *(const ulonglong2*)&Bs[cur][kk][tx * 8 + 4];
            unsigned long long bd[4] = { b01.x, b01.y, b23.x, b23.y };
#pragma unroll
            for (int i = 0; i < 8; i++) {
                unsigned long long ad = pack2(a[i], a[i]);
#pragma unroll
                for (int j = 0; j < 4; j++)
                    acc[i][j] = ffma2(ad, bd[j], acc[i][j]);
            }
        }

        if (kt + 1 < KT) {
            const int nxt = (kt + 1) & 1;
            As[nxt][ak4 + 0][arow] = av.x;
            As[nxt][ak4 + 1][arow] = av.y;
            As[nxt][ak4 + 2][arow] = av.z;
            As[nxt][ak4 + 3][arow] = av.w;
            *(float4*)(&Bs[nxt][wrow][wn4]) = wv;
            if (kt + 2 < KT) {
                const int k0 = (kt + 2) * 8;
                av = *(const float4*)(Ablk + (size_t)arow * Kdim + k0 + ak4);
                wv = *(const float4*)(Wblk + (size_t)(k0 + wrow) * GG + wn4);
            }
            __syncthreads();
        }
    }

    const int row0 = brow * 128 + ty * 8;
    const int col0 = bcol * 128 + tx * 8;
    float bs[8];
#pragma unroll
    for (int j = 0; j < 8; j++) bs[j] = bias1[col0 + j] + bias2[col0 + j];

#pragma unroll
    for (int i = 0; i < 8; i++) {
        float c[8];
#pragma unroll
        for (int j = 0; j < 4; j++) {
            float2 v = unpack2(acc[i][j]);
            c[2*j]   = v.x + bs[2*j];
            c[2*j+1] = v.y + bs[2*j+1];
        }
        *(float4*)(C + (size_t)(row0 + i) * GG + col0)     = *(float4*)&c[0];
        *(float4*)(C + (size_t)(row0 + i) * GG + col0 + 4) = *(float4*)&c[4];
    }
}

// ---------------------------------------------------------------------------
// Startup-only grid barrier
// ---------------------------------------------------------------------------
__device__ __forceinline__ void grid_barrier()
{
    __syncthreads();
    if (threadIdx.x == 0) {
        __threadfence();
        volatile unsigned* vgen = &g_bar_gen;
        unsigned gen = *vgen;
        unsigned arrived = atomicAdd(&g_bar_count, 1u);
        if (arrived == gridDim.x - 1) {
            g_bar_count = 0;
            __threadfence();
            atomicAdd(&g_bar_gen, 1u);
        } else {
            while (*vgen == gen) { }
            __threadfence();
        }
    }
    __syncthreads();
}

// ---------------------------------------------------------------------------
// Persistent LSTM recurrence (R8 structure + 2-chunk pipelined h exchange).
// Block (ug, bg): 16 units x 4 gates x 8 batches.
// Warp 0 polls flags[0..15] (k[0,256)), warp 1 polls flags[16..31]
// (k[256,512)) IN PARALLEL; each issues 8 x 1KB bulk copies on its mbar.
// Compute consumes chunk 0 then chunk 1, overlapping transfer + jitter.
// ---------------------------------------------------------------------------
__global__ void __launch_bounds__(NTHR, 1)
lstm_recur(const float* __restrict__ Wh_l,
           const float* __restrict__ xg,
           float* __restrict__ seq_out,
           float* __restrict__ hc_out,
           int layer)
{
    __shared__ __align__(128) float hs[BPB * 512];   // 16 KB staged h
    __shared__ __align__(8) unsigned long long mbar_store[2];

    const int tid  = threadIdx.x;
    const int wid  = tid >> 5, lane = tid & 31;
    const int ug   = blockIdx.x & 31;
    const int bg   = blockIdx.x >> 5;

    const unsigned mbar0 = (unsigned)__cvta_generic_to_shared(&mbar_store[0]);
    const unsigned mbar1 = mbar0 + 8;
    const unsigned hs_s  = (unsigned)__cvta_generic_to_shared(hs);

    // compute mapping: warp = 2 units x 4 gates x 4 k-phases
    const int u2   = lane & 1;
    const int gate = (lane >> 1) & 3;
    const int s    = lane >> 3;             // k-phase 0..3
    const int ul   = (wid << 1) | u2;
    const int gcol = gate * 512 + ug * 16 + ul;

    // update mapping (lanes 0..15)
    const int uu   = (wid << 1) | (lane & 1);
    const int ubat = lane >> 1;
    const int bglob = bg * 8 + ubat;
    const int uglob = ug * 16 + uu;

    // ---- weights into registers: k = k4*16 + s*4 + {0..3} ----
    unsigned long long w2[64];
    {
#pragma unroll 8
        for (int k4 = 0; k4 < 32; k4++) {
            int kbase = k4 * 16 + s * 4;
            const float* wp = Wh_l + (size_t)kbase * GG + gcol;
            w2[2 * k4]     = pack2(wp[0],      wp[(size_t)GG]);
            w2[2 * k4 + 1] = pack2(wp[2 * GG], wp[(size_t)3 * GG]);
        }
    }

    // ---- init ----
    if (tid == 0) {
        mbar_init(mbar0, 1);
        mbar_init(mbar1, 1);
        g_flags[bg][ug] = 0;
    }
    if (ug == 0) {
        float* hz = &g_hbuf[0][bg * 8 * 512];
        for (int i = tid; i < (8 * 512) / 4; i += NTHR)
            __stcg((float4*)hz + i, make_float4(0.f, 0.f, 0.f, 0.f));
    }
    __syncthreads();

    float creg = 0.f;

    grid_barrier();

    for (int t = 0; t < TT; t++) {
        // prefetch xg for my cell (4 gates), lanes 0..15
        float xgv[4] = {0.f, 0.f, 0.f, 0.f};
        if (lane < 16) {
            const float* xp = xg + ((size_t)bglob * TT + t) * GG + uglob;
            xgv[0] = __ldcg(xp);
            xgv[1] = __ldcg(xp + 512);
            xgv[2] = __ldcg(xp + 1024);
            xgv[3] = __ldcg(xp + 1536);
        }

        // ---- warps 0,1: poll their 16 chunk flags, then 8 x 1KB copies ----
        if (wid < 2) {
            const unsigned mb = wid ? mbar1 : mbar0;
            if (t > 0) {
                const unsigned tok = (unsigned)t;
                const unsigned* fp = &g_flags[bg][wid * 16 + (lane & 15)];
                while (true) {
                    unsigned v = ld_acquire_gpu(fp);
                    if (__all_sync(0xffffffffu, v >= tok)) break;
                }
            }
            if (lane == 0)
                mbar_expect_tx(mb, 8 * 1024);
            __syncwarp();
            if (lane < 8) {
                // row = batch (lane), chunk k-range = [wid*256, wid*256+256)
                bulk_g2s(hs_s + (unsigned)(lane * 2048 + wid * 1024),
                         &g_hbuf[t & 1][(bg * 8 + lane) * 512 + wid * 256],
                         1024, wid ? mbar1 : mbar0);
            }
        }

        // ---- dot products, chunk 0 (k4 0..15) then chunk 1 (k4 16..31) ----
        unsigned long long acc[8];
#pragma unroll
        for (int b = 0; b < 8; b++) acc[b] = 0ull;

        mbar_wait_parity(mbar0, (unsigned)(t & 1));
#pragma unroll
        for (int k4 = 0; k4 < 16; k4++) {
#pragma unroll
            for (int b = 0; b < 8; b++) {
                ulonglong2 h2 = *(const ulonglong2*)&hs[b * 512 + k4 * 16 + s * 4];
                acc[b] = ffma2(h2.x, w2[2 * k4], acc[b]);
                acc[b] = ffma2(h2.y, w2[2 * k4 + 1], acc[b]);
            }
        }
        mbar_wait_parity(mbar1, (unsigned)(t & 1));
#pragma unroll
        for (int k4 = 16; k4 < 32; k4++) {
#pragma unroll
            for (int b = 0; b < 8; b++) {
                ulonglong2 h2 = *(const ulonglong2*)&hs[b * 512 + k4 * 16 + s * 4];
                acc[b] = ffma2(h2.x, w2[2 * k4], acc[b]);
                acc[b] = ffma2(h2.y, w2[2 * k4 + 1], acc[b]);
            }
        }

        // reduce across 4 k-phases (lane bits 3,4)
        float dot[8];
#pragma unroll
        for (int b = 0; b < 8; b++) {
            float2 p = unpack2(acc[b]);
            float v = p.x + p.y;
            v += __shfl_xor_sync(0xffffffffu, v, 8);
            v += __shfl_xor_sync(0xffffffffu, v, 16);
            dot[b] = v;
        }

        // transpose: lane L<16 gathers the 4 gate dots of (unit L&1, batch L>>1)
        float gv[4];
#pragma unroll
        for (int g = 0; g < 4; g++) {
            float got = 0.f;
#pragma unroll
            for (int b = 0; b < 8; b++) {
                float tv = __shfl_sync(0xffffffffu, dot[b], 2 * g + (lane & 1));
                if ((lane >> 1) == b) got = tv;
            }
            gv[g] = got;
        }

        // ---- cell update on lanes 0..15 of every warp ----
        float hval = 0.f;
        if (lane < 16) {
            float f  = fsigmoid(gv[0] + xgv[0]);
            float g  = ftanh   (gv[1] + xgv[1]);
            float ii = fsigmoid(gv[2] + xgv[2]);
            float o  = fsigmoid(gv[3] + xgv[3]);
            creg = f * creg + ii * g;
            hval = o * ftanh(creg);
        }
        // paired h store: even lane stores float2 {unit even, unit odd}
        float hpart = __shfl_xor_sync(0xffffffffu, hval, 1);
        if (lane < 16 && !(lane & 1)) {
            float2 v2 = make_float2(hval, hpart);
            __stcg((float2*)&g_hbuf[(t + 1) & 1][bglob * 512 + ug * 16 + (wid << 1)], v2);
        }
        __syncthreads();

        // ---- publish (release orders the h stores), then lazy outputs ----
        if (tid == 0)
            st_release_gpu(&g_flags[bg][ug], (unsigned)(t + 1));

        if (lane < 16) {
            seq_out[((size_t)bglob * TT + t) * HH + uglob] = hval;
            if (t == TT - 1) {
                hc_out[HOFF + (size_t)(bglob * LLAY + layer) * HH + uglob] = hval;
                hc_out[COFF + (size_t)(bglob * LLAY + layer) * HH + uglob] = creg;
            }
        }
    }
}

// ---------------------------------------------------------------------------
extern "C" void kernel_launch(void* const* d_in, const int* in_sizes, int n_in,
                              void* d_out, int out_size)
{
    const float* x  = (const float*)d_in[0];
    const float* Wx = (const float*)d_in[1];
    const float* bx = (const float*)d_in[2];
    const float* Wh = (const float*)d_in[3];
    const float* bh = (const float*)d_in[4];
    float* out = (float*)d_out;

    float *xg = nullptr, *seq0 = nullptr;
    cudaGetSymbolAddress((void**)&xg, g_xg);
    cudaGetSymbolAddress((void**)&seq0, g_seq0);

    dim3 gdim(GG / 128, MM / 128);

    // Layer 0
    sgemm_bias<<<gdim, 256>>>(x, Wx, bx, bh, xg, DD);
    lstm_recur<<<NBLK, NTHR>>>(Wh, xg, seq0, out, 0);

    // Layer 1
    sgemm_bias<<<gdim, 256>>>(seq0, Wx + (size_t)DD * GG, bx + GG, bh + GG, xg, HH);
    lstm_recur<<<NBLK, NTHR>>>(Wh + (size_t)HH * GG, xg, out, out, 1);
}

// round 14
// speedup vs baseline: 1.1255x; 1.0804x over previous
#include <cuda_runtime.h>
#include <math.h>

// Problem dims
#define BATCH 32
#define TT    1024
#define DD    512
#define HH    512
#define GG    2048
#define LLAY  2
#define MM    (BATCH*TT)

// Output layout in d_out (float32): seq [B,T,H], then h [B,L,H], then c [B,L,H]
#define SEQ_ELEMS  ((size_t)MM*HH)
#define HOFF       (SEQ_ELEMS)
#define COFF       (SEQ_ELEMS + (size_t)BATCH*LLAY*HH)

// Recurrence config: 128 blocks = 32 unit-groups x 4 batch-groups
#define NBLK 128
#define NTHR 512
#define NBG  4
#define NUG  32
#define BPB  8      // batches per block

// Scratch (device globals) — 128B-aligned for cp.async.bulk
__device__ __align__(128) float g_xg[(size_t)MM*GG];
__device__ __align__(128) float g_seq0[(size_t)MM*HH];
__device__ __align__(128) float g_hbuf[2][BATCH*HH];
__device__ unsigned g_flags[NBG][NUG];
__device__ unsigned g_bar_count;
__device__ unsigned g_bar_gen;

// ---------------- packed f32x2 helpers ----------------
__device__ __forceinline__ unsigned long long ffma2(unsigned long long a,
                                                    unsigned long long b,
                                                    unsigned long long c)
{
    unsigned long long d;
    asm("fma.rn.f32x2 %0, %1, %2, %3;" : "=l"(d) : "l"(a), "l"(b), "l"(c));
    return d;
}
__device__ __forceinline__ unsigned long long pack2(float x, float y)
{
    unsigned long long d;
    asm("mov.b64 %0, {%1, %2};" : "=l"(d) : "f"(x), "f"(y));
    return d;
}
__device__ __forceinline__ float2 unpack2(unsigned long long v)
{
    float2 r;
    asm("mov.b64 {%0, %1}, %2;" : "=f"(r.x), "=f"(r.y) : "l"(v));
    return r;
}

// ---------------- fast activations (MUFU-based) ----------------
__device__ __forceinline__ float fsigmoid(float x)
{
    return __fdividef(1.f, 1.f + __expf(-x));
}
__device__ __forceinline__ float ftanh(float x)
{
    return 1.f - __fdividef(2.f, __expf(2.f * x) + 1.f);
}

// ---------------- acquire/release ----------------
__device__ __forceinline__ unsigned ld_acquire_gpu(const unsigned* p)
{
    unsigned v;
    asm volatile("ld.acquire.gpu.global.b32 %0, [%1];" : "=r"(v) : "l"(p) : "memory");
    return v;
}
__device__ __forceinline__ void st_release_gpu(unsigned* p, unsigned v)
{
    asm volatile("st.release.gpu.global.b32 [%0], %1;" :: "l"(p), "r"(v) : "memory");
}

// ---------------- mbarrier + bulk copy ----------------
__device__ __forceinline__ void mbar_init(unsigned mbar, unsigned count)
{
    asm volatile("mbarrier.init.shared.b64 [%0], %1;" :: "r"(mbar), "r"(count) : "memory");
}
__device__ __forceinline__ void mbar_expect_tx(unsigned mbar, unsigned bytes)
{
    asm volatile("mbarrier.arrive.expect_tx.shared.b64 _, [%0], %1;"
                 :: "r"(mbar), "r"(bytes) : "memory");
}
__device__ __forceinline__ void mbar_wait_parity(unsigned mbar, unsigned ph)
{
    asm volatile(
        "{\n\t"
        ".reg .pred P1;\n\t"
        "WAIT_LOOP_%=:\n\t"
        "mbarrier.try_wait.parity.acquire.cta.shared::cta.b64 P1, [%0], %1, 0x989680;\n\t"
        "@P1 bra.uni WAIT_DONE_%=;\n\t"
        "bra.uni WAIT_LOOP_%=;\n\t"
        "WAIT_DONE_%=:\n\t"
        "}"
        :: "r"(mbar), "r"(ph) : "memory");
}
__device__ __forceinline__ void bulk_g2s(unsigned smem_dst, const void* gsrc,
                                         unsigned bytes, unsigned mbar)
{
    asm volatile(
        "cp.async.bulk.shared::cluster.global.mbarrier::complete_tx::bytes "
        "[%0], [%1], %2, [%3];"
        :: "r"(smem_dst), "l"(gsrc), "r"(bytes), "r"(mbar) : "memory");
}

// ---------------------------------------------------------------------------
// SGEMM: C = A @ W + bias1 + bias2. 128x128 tile, BK=8, FFMA2,
// register double-buffer + 2x smem buffers: one __syncthreads per tile.
// ---------------------------------------------------------------------------
__global__ void __launch_bounds__(256, 2)
sgemm_bias(const float* __restrict__ A, const float* __restrict__ W,
           const float* __restrict__ bias1, const float* __restrict__ bias2,
           float* __restrict__ C, int Kdim)
{
    __shared__ __align__(16) float As[2][8][128];
    __shared__ __align__(16) float Bs[2][8][128];

    const int tid = threadIdx.x;
    const int brow = blockIdx.y, bcol = blockIdx.x;

    const float* Ablk = A + (size_t)brow * 128 * Kdim;
    const float* Wblk = W + (size_t)bcol * 128;

    const int arow = tid >> 1;
    const int ak4  = (tid & 1) * 4;
    const int wrow = tid >> 5;
    const int wn4  = (tid & 31) * 4;
    const int ty = tid >> 4;
    const int tx = tid & 15;

    const int KT = Kdim >> 3;

    unsigned long long acc[8][4];
#pragma unroll
    for (int i = 0; i < 8; i++)
#pragma unroll
        for (int j = 0; j < 4; j++) acc[i][j] = 0ull;

    float4 av = *(const float4*)(Ablk + (size_t)arow * Kdim + ak4);
    float4 wv = *(const float4*)(Wblk + (size_t)wrow * GG + wn4);
    As[0][ak4 + 0][arow] = av.x;
    As[0][ak4 + 1][arow] = av.y;
    As[0][ak4 + 2][arow] = av.z;
    As[0][ak4 + 3][arow] = av.w;
    *(float4*)(&Bs[0][wrow][wn4]) = wv;
    if (KT > 1) {
        av = *(const float4*)(Ablk + (size_t)arow * Kdim + 8 + ak4);
        wv = *(const float4*)(Wblk + (size_t)(8 + wrow) * GG + wn4);
    }
    __syncthreads();

    for (int kt = 0; kt < KT; kt++) {
        const int cur = kt & 1;

#pragma unroll
        for (int kk = 0; kk < 8; kk++) {
            float a[8];
            *(float4*)&a[0] = *(const float4*)&As[cur][kk][ty * 8];
            *(float4*)&a[4] = *(const float4*)&As[cur][kk][ty * 8 + 4];
            ulonglong2 b01 = *(const ulonglong2*)&Bs[cur][kk][tx * 8];
            ulonglong2 b23 = *(const ulonglong2*)&Bs[cur][kk][tx * 8 + 4];
            unsigned long long bd[4] = { b01.x, b01.y, b23.x, b23.y };
#pragma unroll
            for (int i = 0; i < 8; i++) {
                unsigned long long ad = pack2(a[i], a[i]);
#pragma unroll
                for (int j = 0; j < 4; j++)
                    acc[i][j] = ffma2(ad, bd[j], acc[i][j]);
            }
        }

        if (kt + 1 < KT) {
            const int nxt = (kt + 1) & 1;
            As[nxt][ak4 + 0][arow] = av.x;
            As[nxt][ak4 + 1][arow] = av.y;
            As[nxt][ak4 + 2][arow] = av.z;
            As[nxt][ak4 + 3][arow] = av.w;
            *(float4*)(&Bs[nxt][wrow][wn4]) = wv;
            if (kt + 2 < KT) {
                const int k0 = (kt + 2) * 8;
                av = *(const float4*)(Ablk + (size_t)arow * Kdim + k0 + ak4);
                wv = *(const float4*)(Wblk + (size_t)(k0 + wrow) * GG + wn4);
            }
            __syncthreads();
        }
    }

    const int row0 = brow * 128 + ty * 8;
    const int col0 = bcol * 128 + tx * 8;
    float bs[8];
#pragma unroll
    for (int j = 0; j < 8; j++) bs[j] = bias1[col0 + j] + bias2[col0 + j];

#pragma unroll
    for (int i = 0; i < 8; i++) {
        float c[8];
#pragma unroll
        for (int j = 0; j < 4; j++) {
            float2 v = unpack2(acc[i][j]);
            c[2*j]   = v.x + bs[2*j];
            c[2*j+1] = v.y + bs[2*j+1];
        }
        *(float4*)(C + (size_t)(row0 + i) * GG + col0)     = *(float4*)&c[0];
        *(float4*)(C + (size_t)(row0 + i) * GG + col0 + 4) = *(float4*)&c[4];
    }
}

// ---------------------------------------------------------------------------
// Startup-only grid barrier
// ---------------------------------------------------------------------------
__device__ __forceinline__ void grid_barrier()
{
    __syncthreads();
    if (threadIdx.x == 0) {
        __threadfence();
        volatile unsigned* vgen = &g_bar_gen;
        unsigned gen = *vgen;
        unsigned arrived = atomicAdd(&g_bar_count, 1u);
        if (arrived == gridDim.x - 1) {
            g_bar_count = 0;
            __threadfence();
            atomicAdd(&g_bar_gen, 1u);
        } else {
            while (*vgen == gen) { }
            __threadfence();
        }
    }
    __syncthreads();
}

// ---------------------------------------------------------------------------
// Persistent LSTM recurrence, 512 threads, 2-chunk pipelined h exchange.
// Block (ug, bg): 16 units x 4 gates x 8 batches; warp w owns unit w
// (its 4 gate cols) x 8 k-phases (lane>>2). Per-thread weights: w2[32]
// (64 regs) — k = k4*32 + s*4 + {0..3}, k4 = 0..15.
// Warp 0 polls flags[0..15] (k<256), warp 8 polls flags[16..31] (k>=256),
// in parallel; each issues 8 x 1KB bulk copies on its own mbar. Compute
// consumes chunk 0 (k4 0..7) then chunk 1 (k4 8..15).
// ---------------------------------------------------------------------------
__global__ void __launch_bounds__(NTHR, 1)
lstm_recur(const float* __restrict__ Wh_l,
           const float* __restrict__ xg,
           float* __restrict__ seq_out,
           float* __restrict__ hc_out,
           int layer)
{
    __shared__ __align__(128) float hs[BPB * 512];   // 16 KB staged h
    __shared__ float gsm[16 * 32];                   // per-warp gate slots
    __shared__ __align__(8) unsigned long long mbar_store[2];

    const int tid  = threadIdx.x;
    const int wid  = tid >> 5, lane = tid & 31;
    const int ug   = blockIdx.x & 31;
    const int bg   = blockIdx.x >> 5;

    const unsigned mbar0 = (unsigned)__cvta_generic_to_shared(&mbar_store[0]);
    const unsigned mbar1 = mbar0 + 8;
    const unsigned hs_s  = (unsigned)__cvta_generic_to_shared(hs);

    // compute mapping: warp = unit (wid), lane = gate (lane&3) | k-phase<<2
    const int gate = lane & 3;
    const int s    = lane >> 2;             // k-phase 0..7
    const int gcol = gate * 512 + ug * 16 + wid;

    // update mapping (lanes 0..7): batch = lane, unit = wid
    const int bglob = bg * 8 + lane;        // valid when lane < 8
    const int uglob = ug * 16 + wid;

    // ---- weights into registers: k = k4*32 + s*4 + {0..3}, k4 = 0..15 ----
    unsigned long long w2[32];
    {
#pragma unroll 4
        for (int k4 = 0; k4 < 16; k4++) {
            int kbase = k4 * 32 + s * 4;
            const float* wp = Wh_l + (size_t)kbase * GG + gcol;
            w2[2 * k4]     = pack2(wp[0],      wp[(size_t)GG]);
            w2[2 * k4 + 1] = pack2(wp[2 * GG], wp[(size_t)3 * GG]);
        }
    }

    // ---- init ----
    if (tid == 0) {
        mbar_init(mbar0, 1);
        mbar_init(mbar1, 1);
        g_flags[bg][ug] = 0;
    }
    if (ug == 0) {
        float* hz = &g_hbuf[0][bg * 8 * 512];
        for (int i = tid; i < (8 * 512) / 4; i += NTHR)
            __stcg((float4*)hz + i, make_float4(0.f, 0.f, 0.f, 0.f));
    }
    __syncthreads();

    float creg = 0.f;

    grid_barrier();

    for (int t = 0; t < TT; t++) {
        // prefetch xg for my cell (4 gates), lanes 0..7
        float xgv[4] = {0.f, 0.f, 0.f, 0.f};
        if (lane < 8) {
            const float* xp = xg + ((size_t)bglob * TT + t) * GG + uglob;
            xgv[0] = __ldcg(xp);
            xgv[1] = __ldcg(xp + 512);
            xgv[2] = __ldcg(xp + 1024);
            xgv[3] = __ldcg(xp + 1536);
        }

        // ---- warps 0 and 8: poll 16 chunk flags each, then 8 x 1KB copies ----
        if (wid == 0 || wid == 8) {
            const int ch = wid >> 3;                 // 0 or 1
            const unsigned mb = ch ? mbar1 : mbar0;
            if (t > 0) {
                const unsigned tok = (unsigned)t;
                const unsigned* fp = &g_flags[bg][ch * 16 + (lane & 15)];
                while (true) {
                    unsigned v = ld_acquire_gpu(fp);
                    if (__all_sync(0xffffffffu, v >= tok)) break;
                }
            }
            if (lane == 0)
                mbar_expect_tx(mb, 8 * 1024);
            __syncwarp();
            if (lane < 8) {
                // row = batch (lane), chunk k-range = [ch*256, ch*256+256)
                bulk_g2s(hs_s + (unsigned)(lane * 2048 + ch * 1024),
                         &g_hbuf[t & 1][(bg * 8 + lane) * 512 + ch * 256],
                         1024, mb);
            }
        }

        // ---- dot products: chunk 0 (k4 0..7), then chunk 1 (k4 8..15) ----
        unsigned long long acc[8];
#pragma unroll
        for (int b = 0; b < 8; b++) acc[b] = 0ull;

        mbar_wait_parity(mbar0, (unsigned)(t & 1));
#pragma unroll
        for (int k4 = 0; k4 < 8; k4++) {
#pragma unroll
            for (int b = 0; b < 8; b++) {
                ulonglong2 h2 = *(const ulonglong2*)&hs[b * 512 + k4 * 32 + s * 4];
                acc[b] = ffma2(h2.x, w2[2 * k4], acc[b]);
                acc[b] = ffma2(h2.y, w2[2 * k4 + 1], acc[b]);
            }
        }
        mbar_wait_parity(mbar1, (unsigned)(t & 1));
#pragma unroll
        for (int k4 = 8; k4 < 16; k4++) {
#pragma unroll
            for (int b = 0; b < 8; b++) {
                ulonglong2 h2 = *(const ulonglong2*)&hs[b * 512 + k4 * 32 + s * 4];
                acc[b] = ffma2(h2.x, w2[2 * k4], acc[b]);
                acc[b] = ffma2(h2.y, w2[2 * k4 + 1], acc[b]);
            }
        }

        // reduce across 8 k-phases (lane bits 2,3,4)
        float dot[8];
#pragma unroll
        for (int b = 0; b < 8; b++) {
            float2 p = unpack2(acc[b]);
            float v = p.x + p.y;
            v += __shfl_xor_sync(0xffffffffu, v, 4);
            v += __shfl_xor_sync(0xffffffffu, v, 8);
            v += __shfl_xor_sync(0xffffffffu, v, 16);
            dot[b] = v;
        }

        // per-warp gate hand-off via smem: lanes 0..3 (one per gate) store
        // 8 batch dots; lanes 0..7 read their 4 gates back.
        if (lane < 4) {
#pragma unroll
            for (int b = 0; b < 8; b++)
                gsm[wid * 32 + gate * 8 + b] = dot[b];
        }
        __syncwarp();

        // ---- cell update on lanes 0..7 of every warp ----
        float hval = 0.f;
        if (lane < 8) {
            float f  = fsigmoid(gsm[wid * 32 +  0 + lane] + xgv[0]);
            float g  = ftanh   (gsm[wid * 32 +  8 + lane] + xgv[1]);
            float ii = fsigmoid(gsm[wid * 32 + 16 + lane] + xgv[2]);
            float o  = fsigmoid(gsm[wid * 32 + 24 + lane] + xgv[3]);
            creg = f * creg + ii * g;
            hval = o * ftanh(creg);
            __stcg(&g_hbuf[(t + 1) & 1][bglob * 512 + uglob], hval);
        }
        __syncthreads();

        // ---- publish (release orders the h stores), then lazy outputs ----
        if (tid == 0)
            st_release_gpu(&g_flags[bg][ug], (unsigned)(t + 1));

        if (lane < 8) {
            seq_out[((size_t)bglob * TT + t) * HH + uglob] = hval;
            if (t == TT - 1) {
                hc_out[HOFF + (size_t)(bglob * LLAY + layer) * HH + uglob] = hval;
                hc_out[COFF + (size_t)(bglob * LLAY + layer) * HH + uglob] = creg;
            }
        }
    }
}

// ---------------------------------------------------------------------------
extern "C" void kernel_launch(void* const* d_in, const int* in_sizes, int n_in,
                              void* d_out, int out_size)
{
    const float* x  = (const float*)d_in[0];
    const float* Wx = (const float*)d_in[1];
    const float* bx = (const float*)d_in[2];
    const float* Wh = (const float*)d_in[3];
    const float* bh = (const float*)d_in[4];
    float* out = (float*)d_out;

    float *xg = nullptr, *seq0 = nullptr;
    cudaGetSymbolAddress((void**)&xg, g_xg);
    cudaGetSymbolAddress((void**)&seq0, g_seq0);

    dim3 gdim(GG / 128, MM / 128);

    // Layer 0
    sgemm_bias<<<gdim, 256>>>(x, Wx, bx, bh, xg, DD);
    lstm_recur<<<NBLK, NTHR>>>(Wh, xg, seq0, out, 0);

    // Layer 1
    sgemm_bias<<<gdim, 256>>>(seq0, Wx + (size_t)DD * GG, bx + GG, bh + GG, xg, HH);
    lstm_recur<<<NBLK, NTHR>>>(Wh + (size_t)HH * GG, xg, out, out, 1);
}